// round 14
// baseline (speedup 1.0000x reference)
#include <cuda_runtime.h>
#include <math.h>
#include <stdint.h>

// Problem constants
#define B 128
#define L 512
#define H 512
#define V 50000

#define NBLK 128
#define NTHR 512

typedef unsigned long long ull;

// ---------------------------------------------------------------------------
// Device globals (static scratch; no runtime allocation)
// ---------------------------------------------------------------------------
__device__ float    g_hT[2][H * B];       // transposed hidden state [k][b], x2
__device__ float    g_c[B * H];           // cell state (segment handoff)
__device__ int      g_tokT[L * B];        // transposed tokens [t][b]
__device__ unsigned g_arrive;             // grid barrier counter
__device__ float    g_xp[(long)L * 2048 * B];  // x_proj + biases: [t][grow][b]

// ---------------------------------------------------------------------------
__device__ __forceinline__ float2 unpackf2(ull v) {
    float2 r; asm("mov.b64 {%0, %1}, %2;" : "=f"(r.x), "=f"(r.y) : "l"(v));
    return r;
}
__device__ __forceinline__ void fma2(ull& d, ull a, ull b) {
    asm("fma.rn.f32x2 %0, %1, %2, %0;" : "+l"(d) : "l"(a), "l"(b));
}
__device__ __forceinline__ float sigf(float x) {
    return 1.f / (1.f + __expf(-x));
}
__device__ __forceinline__ void cpa16(uint32_t dst, const void* src) {
    asm volatile("cp.async.cg.shared.global [%0], [%1], 16;"
                 :: "r"(dst), "l"(src) : "memory");
}

// ---------------------------------------------------------------------------
__global__ void k_init(const int* __restrict__ tokens) {
    int i = blockIdx.x * blockDim.x + threadIdx.x;
    if (i < H * B) { g_hT[0][i] = 0.f; g_hT[1][i] = 0.f; g_c[i] = 0.f; }
    if (i < L * B) {
        int t = i >> 7, b = i & 127;
        g_tokT[i] = tokens[b * L + t];
    }
    if (i == 0) g_arrive = 0u;
}

// ---------------------------------------------------------------------------
// x_proj GEMM: g_xp[t][grow][b] = Wih[grow,:].emb[tok[t][b],:] + bih + bhh
// A staged as pre-duplicated (a,a) pairs -> inner loop has no packf2 MOVs:
// per k: 4 LDS.128 (A-dup) + 2 LDS.128 (B) + 32 fma2.
// ---------------------------------------------------------------------------
__global__ void __launch_bounds__(256, 2)
k_xproj(const float* __restrict__ Wih, const float* __restrict__ bih,
        const float* __restrict__ bhh, const float* __restrict__ emb)
{
    __shared__ float As2[16 * 264];   // dup pairs: row k holds 128*(a,a)
    __shared__ float Bs[16 * 132];
    __shared__ float bsum[128];
    __shared__ int   tok[128];

    const int gt  = blockIdx.x;     // grow tile 0..15
    const int t   = blockIdx.y;     // timestep 0..511
    const int tid = threadIdx.x;
    const int ty  = tid >> 4;
    const int tx  = tid & 15;

    if (tid < 128) {
        tok[tid]  = g_tokT[t * 128 + tid];
        int grow  = gt * 128 + tid;
        bsum[tid] = bih[grow] + bhh[grow];
    }
    __syncthreads();

    ull acc[8][4];
    #pragma unroll
    for (int i = 0; i < 8; i++)
        #pragma unroll
        for (int j = 0; j < 4; j++) acc[i][j] = 0ull;

    for (int k0 = 0; k0 < 512; k0 += 16) {
        // stage A (dup pairs): 128 grows x 16 k
        #pragma unroll
        for (int i = 0; i < 2; i++) {
            int idx = tid + 256 * i;
            int r = idx >> 2, f = idx & 3;
            float4 w4 = *(const float4*)(Wih + (gt * 128 + r) * 512 + k0 + 4 * f);
            *(float2*)(As2 + (4 * f + 0) * 264 + 2 * r) = make_float2(w4.x, w4.x);
            *(float2*)(As2 + (4 * f + 1) * 264 + 2 * r) = make_float2(w4.y, w4.y);
            *(float2*)(As2 + (4 * f + 2) * 264 + 2 * r) = make_float2(w4.z, w4.z);
            *(float2*)(As2 + (4 * f + 3) * 264 + 2 * r) = make_float2(w4.w, w4.w);
        }
        // stage B: 128 b x 16 k (embedding gather)
        #pragma unroll
        for (int i = 0; i < 2; i++) {
            int idx = tid + 256 * i;
            int b = idx >> 2, f = idx & 3;
            float4 v4 = *(const float4*)(emb + (long)tok[b] * 512 + k0 + 4 * f);
            Bs[(4 * f + 0) * 132 + b] = v4.x;
            Bs[(4 * f + 1) * 132 + b] = v4.y;
            Bs[(4 * f + 2) * 132 + b] = v4.z;
            Bs[(4 * f + 3) * 132 + b] = v4.w;
        }
        __syncthreads();

        #pragma unroll
        for (int k = 0; k < 16; k++) {
            ulonglong2 a01 = *(const ulonglong2*)(As2 + k * 264 + ty * 16);
            ulonglong2 a23 = *(const ulonglong2*)(As2 + k * 264 + ty * 16 + 4);
            ulonglong2 a45 = *(const ulonglong2*)(As2 + k * 264 + ty * 16 + 8);
            ulonglong2 a67 = *(const ulonglong2*)(As2 + k * 264 + ty * 16 + 12);
            ulonglong2 b01 = *(const ulonglong2*)(Bs + k * 132 + tx * 8);
            ulonglong2 b23 = *(const ulonglong2*)(Bs + k * 132 + tx * 8 + 4);
            ull ad[8] = {a01.x, a01.y, a23.x, a23.y, a45.x, a45.y, a67.x, a67.y};
            #pragma unroll
            for (int i = 0; i < 8; i++) {
                fma2(acc[i][0], ad[i], b01.x);
                fma2(acc[i][1], ad[i], b01.y);
                fma2(acc[i][2], ad[i], b23.x);
                fma2(acc[i][3], ad[i], b23.y);
            }
        }
        __syncthreads();
    }

    float* outp = g_xp + (long)t * 262144 + (gt * 128) * 128;
    #pragma unroll
    for (int i = 0; i < 8; i++) {
        int r = ty * 8 + i;
        float bias = bsum[r];
        float2 p0 = unpackf2(acc[i][0]), p1 = unpackf2(acc[i][1]);
        float2 p2 = unpackf2(acc[i][2]), p3 = unpackf2(acc[i][3]);
        float4 o0 = make_float4(p0.x + bias, p0.y + bias, p1.x + bias, p1.y + bias);
        float4 o1 = make_float4(p2.x + bias, p2.y + bias, p3.x + bias, p3.y + bias);
        *(float4*)(outp + r * 128 + tx * 8)     = o0;
        *(float4*)(outp + r * 128 + tx * 8 + 4) = o1;
    }
}

// ---------------------------------------------------------------------------
// Persistent LSTM recurrence over t in [t0, t1). K = 512 (h half only).
// Block bx owns h-cols [4bx,4bx+4) -> 16 gate rows; dup-weight table in smem.
// 16 warps = 4 K-sets (128 k) x 4 batch-groups (32 b). Per k: LDS.128(a) +
// 2x LDS.128(dup w) + 8 fma2. Staging: cp.async.cg (L2-direct), 2-deep
// pipeline over 3 buffers, set-local named barriers. Grid barrier: cg-style.
// ---------------------------------------------------------------------------
extern __shared__ float smem[];

__global__ void __launch_bounds__(NTHR, 1)
k_lstm(const int* __restrict__ lengths, const float* __restrict__ Whh,
       int t0, int t1)
{
    float* Wd = smem;                  // [512][32] dup (w,w) pairs = 16384 fl
    float* As = Wd + 16384;            // [4 sets][3 buf][16 k][132]
    float* Gs = As + 4 * 3 * 16 * 132; // [4 sets][16][132] partials

    const int tid  = threadIdx.x;
    const int bx   = blockIdx.x;
    const int w    = tid >> 5;
    const int lane = tid & 31;

    // ---- dup-weight table (W_hh only, K=512) ----
    for (int idx = tid; idx < 16 * 512; idx += NTHR) {
        int k  = idx >> 4;
        int lr = idx & 15;
        int g = lr >> 2, cc = lr & 3;
        int grow = g * 512 + bx * 4 + cc;
        float wv = Whh[grow * 512 + k];
        Wd[k * 32 + 2 * lr]     = wv;
        Wd[k * 32 + 2 * lr + 1] = wv;
    }

    // ---- warp roles ----
    const int set = w & 3;             // K-set: k in [128set, 128set+128)
    const int w4  = w >> 2;            // 0..3: batch group [32w4, 32w4+32)
    const int kb0 = 128 * set;
    float* AsS = As + set * (3 * 16 * 132);
    const uint32_t asS_u32 = (uint32_t)__cvta_generic_to_shared(AsS);

    const int r4 = lane & 3;           // rows 4r4..4r4+3
    const int bq = lane >> 2;          // 0..7: 4-batch quad within group

    // ---- pointwise roles ----
    const int pb = tid >> 2;           // batch 0..127
    const int pc = tid & 3;
    const int hcol = bx * 4 + pc;
    const int len  = lengths[pb];
    float c_reg = g_c[pb * H + hcol];
    float h_reg = g_hT[t0 & 1][hcol * 128 + pb];

    __syncthreads();

    for (int t = t0; t < t1; t++) {
        const int rb = t & 1, wb = rb ^ 1;
        const float* __restrict__ hT = g_hT[rb];

        // prefetch x_proj for my (pb, pc)
        float xq[4];
        #pragma unroll
        for (int g = 0; g < 4; g++)
            xq[g] = __ldg(g_xp + (long)t * 262144
                          + (g * 512 + bx * 4 + pc) * 128 + pb);

        ull acc[8];
        #pragma unroll
        for (int i = 0; i < 8; i++) acc[i] = 0ull;

        // ---- prologue: issue chunks 0 and 1 (each = own commit group) ----
        #pragma unroll
        for (int cc = 0; cc < 2; cc++) {
            #pragma unroll
            for (int m = 0; m < 4; m++) {
                int kg = kb0 + 16 * cc + 4 * w4 + m;
                uint32_t dst = asS_u32
                    + (uint32_t)((cc * (16 * 132) + (4 * w4 + m) * 132
                                  + 4 * lane) * 4);
                cpa16(dst, hT + kg * 128 + 4 * lane);
            }
            asm volatile("cp.async.commit_group;" ::: "memory");
        }

        for (int c = 0; c < 8; c++) {
            // wait for my chunk-c group, then publish set-wide
            if (c < 7) asm volatile("cp.async.wait_group 1;" ::: "memory");
            else       asm volatile("cp.async.wait_group 0;" ::: "memory");
            asm volatile("bar.sync %0, %1;" :: "r"(1 + set), "r"(128) : "memory");

            // issue chunk c+2 into buf (c+2)%3 (freed: all set-warps are
            // past compute of chunk c-1, which used that buffer)
            if (c + 2 < 8) {
                int cc = c + 2;
                int bufo = (cc % 3) * (16 * 132);
                #pragma unroll
                for (int m = 0; m < 4; m++) {
                    int kg = kb0 + 16 * cc + 4 * w4 + m;
                    uint32_t dst = asS_u32
                        + (uint32_t)((bufo + (4 * w4 + m) * 132
                                      + 4 * lane) * 4);
                    cpa16(dst, hT + kg * 128 + 4 * lane);
                }
                asm volatile("cp.async.commit_group;" ::: "memory");
            }

            // compute chunk c (16 k)
            {
                const float* Ab = AsS + (c % 3) * (16 * 132) + 32 * w4 + 4 * bq;
                const float* Wk = Wd + (kb0 + 16 * c) * 32 + 8 * r4;
                #pragma unroll
                for (int k = 0; k < 16; k++) {
                    ulonglong2 a   = *(const ulonglong2*)(Ab + k * 132);
                    ulonglong2 w01 = *(const ulonglong2*)(Wk + k * 32);
                    ulonglong2 w23 = *(const ulonglong2*)(Wk + k * 32 + 4);
                    fma2(acc[0], a.x, w01.x);  fma2(acc[1], a.y, w01.x);
                    fma2(acc[2], a.x, w01.y);  fma2(acc[3], a.y, w01.y);
                    fma2(acc[4], a.x, w23.x);  fma2(acc[5], a.y, w23.x);
                    fma2(acc[6], a.x, w23.y);  fma2(acc[7], a.y, w23.y);
                }
            }
        }

        // ---- park partial tiles ----
        #pragma unroll
        for (int r = 0; r < 4; r++) {
            ulonglong2 pr; pr.x = acc[2 * r]; pr.y = acc[2 * r + 1];
            *(ulonglong2*)(Gs + set * (16 * 132) + (4 * r4 + r) * 132
                           + 32 * w4 + 4 * bq) = pr;
        }
        __syncthreads();

        // ---- reduce 4 K-set partials + x_proj + gates ----
        {
            float xi = xq[0], xf = xq[1], xg = xq[2], xo = xq[3];
            #pragma unroll
            for (int s = 0; s < 4; s++) {
                const float* P = Gs + s * (16 * 132);
                xi += P[(0 + pc)  * 132 + pb];
                xf += P[(4 + pc)  * 132 + pb];
                xg += P[(8 + pc)  * 132 + pb];
                xo += P[(12 + pc) * 132 + pb];
            }
            if (t < len) {
                float ig = sigf(xi), fg = sigf(xf), og = sigf(xo);
                float gg = 2.f * sigf(2.f * xg) - 1.f;
                c_reg = fg * c_reg + ig * gg;
                h_reg = og * (2.f * sigf(2.f * c_reg) - 1.f);
            }
            __stcg(&g_hT[wb][hcol * 128 + pb], h_reg);
        }

        // ---- grid barrier: cg-style, tid0 only ----
        __syncthreads();
        if (tid == 0) {
            asm volatile("fence.acq_rel.gpu;" ::: "memory");
            atomicAdd(&g_arrive, 1u);
            unsigned target = (unsigned)NBLK * (unsigned)(t + 1);
            unsigned cur;
            do {
                asm volatile("ld.acquire.gpu.global.u32 %0, [%1];"
                             : "=r"(cur) : "l"(&g_arrive));
            } while (cur < target);
        }
        __syncthreads();
    }

    // ---- segment handoff ----
    g_c[pb * H + hcol] = c_reg;
}

// ---------------------------------------------------------------------------
// FC: out[b, v] = h_final[b, :] . W_fc[v, :] + b_fc[v]   (h from g_hT[0])
// ---------------------------------------------------------------------------
__global__ void __launch_bounds__(256, 1)
k_fc(const float* __restrict__ Wfc, const float* __restrict__ bfc,
     float* __restrict__ out)
{
    __shared__ float As_[16][128];
    __shared__ float Bs_[16][128];

    const int vBase = blockIdx.x * 128;
    const int tid   = threadIdx.x;
    const int ty    = tid >> 4;
    const int tx    = tid & 15;

    const float* __restrict__ hT = g_hT[0];

    float acc[8][8];
    #pragma unroll
    for (int i = 0; i < 8; i++)
        #pragma unroll
        for (int j = 0; j < 8; j++) acc[i][j] = 0.f;

    for (int k0 = 0; k0 < H; k0 += 16) {
        #pragma unroll
        for (int r = 0; r < 8; r++) {
            int idx = tid + 256 * r;
            int k = idx >> 7, m = idx & 127;
            As_[k][m] = hT[(k0 + k) * 128 + m];
        }
        #pragma unroll
        for (int r = 0; r < 8; r++) {
            int idx = tid + 256 * r;
            int vv = idx >> 4, k = idx & 15;
            int gv = vBase + vv;
            Bs_[k][vv] = (gv < V) ? Wfc[gv * H + k0 + k] : 0.f;
        }
        __syncthreads();

        #pragma unroll
        for (int k = 0; k < 16; k++) {
            float a[8], b[8];
            *(float4*)&a[0] = *(const float4*)&As_[k][ty * 8];
            *(float4*)&a[4] = *(const float4*)&As_[k][ty * 8 + 4];
            *(float4*)&b[0] = *(const float4*)&Bs_[k][tx * 8];
            *(float4*)&b[4] = *(const float4*)&Bs_[k][tx * 8 + 4];
            #pragma unroll
            for (int i = 0; i < 8; i++)
                #pragma unroll
                for (int j = 0; j < 8; j++)
                    acc[i][j] = fmaf(a[i], b[j], acc[i][j]);
        }
        __syncthreads();
    }

    #pragma unroll
    for (int i = 0; i < 8; i++) {
        int m = ty * 8 + i;
        #pragma unroll
        for (int j = 0; j < 8; j++) {
            int gv = vBase + tx * 8 + j;
            if (gv < V) out[m * V + gv] = acc[i][j] + bfc[gv];
        }
    }
}

// ---------------------------------------------------------------------------
extern "C" void kernel_launch(void* const* d_in, const int* in_sizes, int n_in,
                              void* d_out, int out_size)
{
    const int*   tokens  = (const int*)  d_in[0];
    const int*   lengths = (const int*)  d_in[1];
    const float* emb     = (const float*)d_in[2];
    const float* Wih     = (const float*)d_in[3];
    const float* Whh     = (const float*)d_in[4];
    const float* bih     = (const float*)d_in[5];
    const float* bhh     = (const float*)d_in[6];
    const float* Wfc     = (const float*)d_in[7];
    const float* bfc     = (const float*)d_in[8];
    float* out = (float*)d_out;

    const int smemBytes = (16384 + 4 * 3 * 16 * 132 + 4 * 16 * 132) * 4;
    static bool attrSet = false;
    if (!attrSet) {
        cudaFuncSetAttribute(k_lstm, cudaFuncAttributeMaxDynamicSharedMemorySize,
                             smemBytes);
        attrSet = true;
    }

    k_init<<<(H * B + 255) / 256, 256>>>(tokens);
    dim3 xg(16, 512);
    k_xproj<<<xg, 256>>>(Wih, bih, bhh, emb);
    for (int seg = 0; seg < 4; seg++) {
        k_lstm<<<NBLK, NTHR, smemBytes>>>(lengths, Whh,
                                          seg * (L / 4), (seg + 1) * (L / 4));
    }
    k_fc<<<(V + 127) / 128, 256>>>(Wfc, bfc, out);
}